// round 1
// baseline (speedup 1.0000x reference)
#include <cuda_runtime.h>

// GCN_82360292868212: 3-layer GraphConv (DGL norm='both') + linear + softmax.
// N = 1,000,000 nodes, E = 8,000,000 edges, feature dims 1 -> 4 -> 4 -> 4 -> 2.
//
// Strategy:
//  * aggregate PRE-projection (linearity of W): layer-1 edge pass is scalar.
//  * degrees once (shared by all layers).
//  * layer-2/3 edge passes use red.global.add.v4.f32 (one vector reduction
//    per edge, no return value -> REDG, no ATOMG round trip).
//  * all node-sized scratch lives in __device__ globals (no allocation).

#define NMAX 1000000
#define NT   256

__device__ int    g_deg_src[NMAX];
__device__ int    g_deg_dst[NMAX];
__device__ float  g_norm_src[NMAX];
__device__ float  g_norm_dst[NMAX];
__device__ float  g_s1[NMAX];        // layer-1 pre-projection scalar feature
__device__ float  g_agg1[NMAX];      // layer-1 scalar aggregate
__device__ float4 g_s[NMAX];         // layer-2/3 pre-projection features
__device__ float4 g_agg[NMAX];       // layer-2/3 aggregates (reused)

// ---------------------------------------------------------------------------
__global__ void k_init(int n) {
    int i = blockIdx.x * blockDim.x + threadIdx.x;
    if (i < n) {
        g_deg_src[i] = 0;
        g_deg_dst[i] = 0;
        g_agg1[i]    = 0.0f;
        g_agg[i]     = make_float4(0.f, 0.f, 0.f, 0.f);
    }
}

// Degree counting: out-degree of src, in-degree of dst.
__global__ void k_degree(const int* __restrict__ src,
                         const int* __restrict__ dst, int e) {
    int i = blockIdx.x * blockDim.x + threadIdx.x;
    if (i < e) {
        atomicAdd(&g_deg_src[src[i]], 1);   // unused result -> REDG
        atomicAdd(&g_deg_dst[dst[i]], 1);
    }
}

// norms + layer-1 scaled input (scalar feature).
__global__ void k_norm_s1(const float* __restrict__ x, int n) {
    int i = blockIdx.x * blockDim.x + threadIdx.x;
    if (i < n) {
        int ds = g_deg_src[i], dd = g_deg_dst[i];
        float ns = (ds > 0) ? rsqrtf((float)ds) : 0.0f;
        float nd = (dd > 0) ? rsqrtf((float)dd) : 0.0f;
        g_norm_src[i] = ns;
        g_norm_dst[i] = nd;
        g_s1[i] = x[i] * ns;
    }
}

// layer-1 edge pass: scalar scatter-add.
__global__ void k_edge1(const int* __restrict__ src,
                        const int* __restrict__ dst, int e) {
    int i = blockIdx.x * blockDim.x + threadIdx.x;
    if (i < e) {
        float v = __ldg(&g_s1[src[i]]);
        atomicAdd(&g_agg1[dst[i]], v);      // REDG
    }
}

// layer-1 node epilogue: project scalar aggregate through W1 [1,4],
// scale by dst-norm, add bias, relu; emit scaled features for layer 2.
__global__ void k_node1(const float* __restrict__ W1,
                        const float* __restrict__ b1, int n) {
    int i = blockIdx.x * blockDim.x + threadIdx.x;
    if (i >= n) return;
    float  a  = g_agg1[i];
    float  nd = g_norm_dst[i];
    float  ns = g_norm_src[i];
    float4 w  = *reinterpret_cast<const float4*>(W1);
    float4 b  = *reinterpret_cast<const float4*>(b1);
    float x0 = fmaxf(a * w.x * nd + b.x, 0.f);
    float x1 = fmaxf(a * w.y * nd + b.y, 0.f);
    float x2 = fmaxf(a * w.z * nd + b.z, 0.f);
    float x3 = fmaxf(a * w.w * nd + b.w, 0.f);
    g_s[i] = make_float4(x0 * ns, x1 * ns, x2 * ns, x3 * ns);
}

// layer-2/3 edge pass: float4 gather + single vector reduction per edge.
__global__ void k_edge4(const int* __restrict__ src,
                        const int* __restrict__ dst, int e) {
    int i = blockIdx.x * blockDim.x + threadIdx.x;
    if (i < e) {
        float4 v = __ldg(&g_s[src[i]]);
        float4* p = &g_agg[dst[i]];
        asm volatile("red.global.add.v4.f32 [%0], {%1, %2, %3, %4};"
                     :: "l"(p), "f"(v.x), "f"(v.y), "f"(v.z), "f"(v.w)
                     : "memory");
    }
}

// mid-layer node epilogue: out = relu((agg @ W [4,4]) * nd + b);
// emit scaled features for the next layer and re-zero the aggregate buffer.
__global__ void k_node_mid(const float* __restrict__ W,
                           const float* __restrict__ b, int n) {
    int i = blockIdx.x * blockDim.x + threadIdx.x;
    if (i >= n) return;
    float4 v = g_agg[i];
    g_agg[i] = make_float4(0.f, 0.f, 0.f, 0.f);   // ready for next edge pass
    float nd = g_norm_dst[i];
    float ns = g_norm_src[i];
    float4 w0 = *reinterpret_cast<const float4*>(W + 0);
    float4 w1 = *reinterpret_cast<const float4*>(W + 4);
    float4 w2 = *reinterpret_cast<const float4*>(W + 8);
    float4 w3 = *reinterpret_cast<const float4*>(W + 12);
    float4 bb = *reinterpret_cast<const float4*>(b);
    float o0 = v.x * w0.x + v.y * w1.x + v.z * w2.x + v.w * w3.x;
    float o1 = v.x * w0.y + v.y * w1.y + v.z * w2.y + v.w * w3.y;
    float o2 = v.x * w0.z + v.y * w1.z + v.z * w2.z + v.w * w3.z;
    float o3 = v.x * w0.w + v.y * w1.w + v.z * w2.w + v.w * w3.w;
    o0 = fmaxf(o0 * nd + bb.x, 0.f);
    o1 = fmaxf(o1 * nd + bb.y, 0.f);
    o2 = fmaxf(o2 * nd + bb.z, 0.f);
    o3 = fmaxf(o3 * nd + bb.w, 0.f);
    g_s[i] = make_float4(o0 * ns, o1 * ns, o2 * ns, o3 * ns);
}

// final node epilogue: layer-3 (no relu) + linear [4,2] + softmax(2).
__global__ void k_final(const float* __restrict__ W3,
                        const float* __restrict__ b3,
                        const float* __restrict__ Wl,
                        const float* __restrict__ bl,
                        float* __restrict__ out, int n) {
    int i = blockIdx.x * blockDim.x + threadIdx.x;
    if (i >= n) return;
    float4 v = g_agg[i];
    float nd = g_norm_dst[i];
    float4 w0 = *reinterpret_cast<const float4*>(W3 + 0);
    float4 w1 = *reinterpret_cast<const float4*>(W3 + 4);
    float4 w2 = *reinterpret_cast<const float4*>(W3 + 8);
    float4 w3 = *reinterpret_cast<const float4*>(W3 + 12);
    float4 bb = *reinterpret_cast<const float4*>(b3);
    float x0 = (v.x * w0.x + v.y * w1.x + v.z * w2.x + v.w * w3.x) * nd + bb.x;
    float x1 = (v.x * w0.y + v.y * w1.y + v.z * w2.y + v.w * w3.y) * nd + bb.y;
    float x2 = (v.x * w0.z + v.y * w1.z + v.z * w2.z + v.w * w3.z) * nd + bb.z;
    float x3 = (v.x * w0.w + v.y * w1.w + v.z * w2.w + v.w * w3.w) * nd + bb.w;
    // Wl is [4,2] row-major: Wl[r*2 + c]
    float l0 = x0 * __ldg(Wl + 0) + x1 * __ldg(Wl + 2) + x2 * __ldg(Wl + 4)
             + x3 * __ldg(Wl + 6) + __ldg(bl + 0);
    float l1 = x0 * __ldg(Wl + 1) + x1 * __ldg(Wl + 3) + x2 * __ldg(Wl + 5)
             + x3 * __ldg(Wl + 7) + __ldg(bl + 1);
    float m  = fmaxf(l0, l1);
    float e0 = __expf(l0 - m);
    float e1 = __expf(l1 - m);
    float inv = 1.0f / (e0 + e1);
    out[2 * i + 0] = e0 * inv;
    out[2 * i + 1] = e1 * inv;
}

// ---------------------------------------------------------------------------
extern "C" void kernel_launch(void* const* d_in, const int* in_sizes, int n_in,
                              void* d_out, int out_size) {
    const float* in_feat = (const float*)d_in[0];
    const int*   src     = (const int*)  d_in[1];
    const int*   dst     = (const int*)  d_in[2];
    const float* W1      = (const float*)d_in[3];
    const float* b1      = (const float*)d_in[4];
    const float* W2      = (const float*)d_in[5];
    const float* b2      = (const float*)d_in[6];
    const float* W3      = (const float*)d_in[7];
    const float* b3      = (const float*)d_in[8];
    const float* Wl      = (const float*)d_in[9];
    const float* bl      = (const float*)d_in[10];
    float* out = (float*)d_out;

    int n = in_sizes[0];   // N nodes (in_feat is [N,1])
    int e = in_sizes[1];   // E edges

    int gn = (n + NT - 1) / NT;
    int ge = (e + NT - 1) / NT;

    k_init<<<gn, NT>>>(n);
    k_degree<<<ge, NT>>>(src, dst, e);
    k_norm_s1<<<gn, NT>>>(in_feat, n);
    k_edge1<<<ge, NT>>>(src, dst, e);
    k_node1<<<gn, NT>>>(W1, b1, n);
    k_edge4<<<ge, NT>>>(src, dst, e);          // layer 2 aggregation
    k_node_mid<<<gn, NT>>>(W2, b2, n);
    k_edge4<<<ge, NT>>>(src, dst, e);          // layer 3 aggregation
    k_final<<<gn, NT>>>(W3, b3, Wl, bl, out, n);
}